// round 1
// baseline (speedup 1.0000x reference)
#include <cuda_runtime.h>

#define Dm 128
#define EPSn 1e-5f

// scratch: Nt x 128 accumulator (Nt = 100000 for this problem)
__device__ float g_tf[100000 * 128];

__device__ __forceinline__ float warp_sum(float v) {
    v += __shfl_xor_sync(0xffffffffu, v, 16);
    v += __shfl_xor_sync(0xffffffffu, v, 8);
    v += __shfl_xor_sync(0xffffffffu, v, 4);
    v += __shfl_xor_sync(0xffffffffu, v, 2);
    v += __shfl_xor_sync(0xffffffffu, v, 1);
    return v;
}

// ---------------------------------------------------------------------------
// K1: g_tf = target_feat @ W_in   (Nt x 128) @ (128 x 128)
// blockDim = 256 (8 warps). Each warp handles 4 rows; lane owns outputs
// j = 4*lane .. 4*lane+3 (float4 W loads from shared).
// smem: W (16384 f) + xs (8*4*128 f) = 81920 B
// ---------------------------------------------------------------------------
extern "C" __global__ void __launch_bounds__(256)
k1_proj(const float* __restrict__ tfeat, const float* __restrict__ Win, int Nt) {
    extern __shared__ float sm[];
    float* Ws = sm;                  // 16384 floats
    float* xs = sm + Dm * Dm;        // 8*4*128 floats

    int tid = threadIdx.x;
    {
        const float4* a = (const float4*)Win;
        float4* b = (float4*)Ws;
        for (int i = tid; i < Dm * Dm / 4; i += blockDim.x) b[i] = a[i];
    }
    __syncthreads();

    int lane = tid & 31, warp = tid >> 5;
    float* xw = xs + warp * 4 * Dm;
    const float4* W4 = (const float4*)Ws;
    const float4* x4 = (const float4*)tfeat;

    int nwarp = blockDim.x >> 5;
    int gw = blockIdx.x * nwarp + warp;
    int wt = gridDim.x * nwarp;

    for (int base = gw * 4; base < Nt; base += wt * 4) {
        int ne = min(4, Nt - base);
#pragma unroll
        for (int e = 0; e < 4; e++) {
            int r = base + ((e < ne) ? e : 0);
            ((float4*)(xw + e * Dm))[lane] = x4[r * 32 + lane];
        }
        __syncwarp();
        float4 acc[4];
#pragma unroll
        for (int e = 0; e < 4; e++) acc[e] = make_float4(0.f, 0.f, 0.f, 0.f);
#pragma unroll 4
        for (int k = 0; k < Dm; k++) {
            float4 w = W4[k * 32 + lane];
#pragma unroll
            for (int e = 0; e < 4; e++) {
                float xv = xw[e * Dm + k];
                acc[e].x += xv * w.x; acc[e].y += xv * w.y;
                acc[e].z += xv * w.z; acc[e].w += xv * w.w;
            }
        }
#pragma unroll
        for (int e = 0; e < 4; e++)
            if (e < ne) ((float4*)(g_tf + (base + e) * Dm))[lane] = acc[e];
        __syncwarp();
    }
}

// ---------------------------------------------------------------------------
// K2: edge pipeline.
//   dist = relu((cpose[hi]-tpose[wi]) @ W_rp + b_rp)        [E,128]
//   x    = [cfeat[hi] | dist]                               [E,256]
//   h    = relu(GN(x @ W_ctx1))                             [E,128]
//   ctx  = h @ W_ctx2                                       [E,128]
//   atomicAdd g_tf[wi] += ctx
// blockDim = 192 (6 warps), each warp processes 4 edges at a time.
// smem floats: Wrp 512 | brp 128 | g 128 | be 128 | W1 32768 | W2 16384 |
//              xs 6*4*256   -> 56192 floats = 224768 B
// ---------------------------------------------------------------------------
extern "C" __global__ void __launch_bounds__(192)
k2_edge(const float* __restrict__ cfeat, const float* __restrict__ cpose,
        const float* __restrict__ tpose, const int* __restrict__ hi,
        const int* __restrict__ wi, const float* __restrict__ Wrp,
        const float* __restrict__ brp, const float* __restrict__ W1,
        const float* __restrict__ gc, const float* __restrict__ bc,
        const float* __restrict__ W2, int E) {
    extern __shared__ float sm[];
    float* Wrp_s = sm;               // 512
    float* brp_s = Wrp_s + 512;      // 128
    float* gc_s  = brp_s + 128;      // 128
    float* bc_s  = gc_s + 128;       // 128
    float* W1_s  = bc_s + 128;       // 32768
    float* W2_s  = W1_s + 32768;     // 16384
    float* xs    = W2_s + 16384;     // 6*4*256

    int tid = threadIdx.x;
    for (int i = tid; i < 512; i += blockDim.x) Wrp_s[i] = Wrp[i];
    for (int i = tid; i < 128; i += blockDim.x) {
        brp_s[i] = brp[i]; gc_s[i] = gc[i]; bc_s[i] = bc[i];
    }
    {
        const float4* a = (const float4*)W1; float4* b = (float4*)W1_s;
        for (int i = tid; i < 8192; i += blockDim.x) b[i] = a[i];
        const float4* c = (const float4*)W2; float4* d = (float4*)W2_s;
        for (int i = tid; i < 4096; i += blockDim.x) d[i] = c[i];
    }
    __syncthreads();

    int lane = tid & 31, warp = tid >> 5;
    float* xw = xs + warp * 4 * 256;
    const float4* W14  = (const float4*)W1_s;
    const float4* W24  = (const float4*)W2_s;
    const float4* Wrp4 = (const float4*)Wrp_s;
    const float4* brp4 = (const float4*)brp_s;
    const float4* gc4  = (const float4*)gc_s;
    const float4* bc4  = (const float4*)bc_s;
    const float4* cf4  = (const float4*)cfeat;
    const float4* cp4  = (const float4*)cpose;
    const float4* tp4  = (const float4*)tpose;

    int gw = blockIdx.x * 6 + warp;
    int wt = gridDim.x * 6;

    for (int base = gw * 4; base < E; base += wt * 4) {
        int ne = min(4, E - base);
        int hidx[4], widx[4];
#pragma unroll
        for (int e = 0; e < 4; e++) {
            int idx = base + ((e < ne) ? e : 0);
            hidx[e] = hi[idx]; widx[e] = wi[idx];
        }
        // gather context feats -> xs[e][0:128]
#pragma unroll
        for (int e = 0; e < 4; e++)
            ((float4*)(xw + e * 256))[lane] = cf4[hidx[e] * 32 + lane];
        // relpose MLP -> xs[e][128:256]
#pragma unroll
        for (int e = 0; e < 4; e++) {
            float4 cp = cp4[hidx[e]], tp = tp4[widx[e]];
            float d0 = cp.x - tp.x, d1 = cp.y - tp.y;
            float d2 = cp.z - tp.z, d3 = cp.w - tp.w;
            float4 a = brp4[lane];
            float4 w0 = Wrp4[lane],      w1 = Wrp4[32 + lane];
            float4 w2 = Wrp4[64 + lane], w3 = Wrp4[96 + lane];
            a.x += d0 * w0.x + d1 * w1.x + d2 * w2.x + d3 * w3.x;
            a.y += d0 * w0.y + d1 * w1.y + d2 * w2.y + d3 * w3.y;
            a.z += d0 * w0.z + d1 * w1.z + d2 * w2.z + d3 * w3.z;
            a.w += d0 * w0.w + d1 * w1.w + d2 * w2.w + d3 * w3.w;
            a.x = fmaxf(a.x, 0.f); a.y = fmaxf(a.y, 0.f);
            a.z = fmaxf(a.z, 0.f); a.w = fmaxf(a.w, 0.f);
            ((float4*)(xw + e * 256 + 128))[lane] = a;
        }
        __syncwarp();

        // GEMM1: [4,256] @ [256,128]
        float4 acc[4];
#pragma unroll
        for (int e = 0; e < 4; e++) acc[e] = make_float4(0.f, 0.f, 0.f, 0.f);
#pragma unroll 4
        for (int k = 0; k < 256; k++) {
            float4 w = W14[k * 32 + lane];
#pragma unroll
            for (int e = 0; e < 4; e++) {
                float xv = xw[e * 256 + k];
                acc[e].x += xv * w.x; acc[e].y += xv * w.y;
                acc[e].z += xv * w.z; acc[e].w += xv * w.w;
            }
        }
        // GN + relu -> h stored in xs[e][0:128]
#pragma unroll
        for (int e = 0; e < 4; e++) {
            float s1 = acc[e].x + acc[e].y + acc[e].z + acc[e].w;
            float s2 = acc[e].x * acc[e].x + acc[e].y * acc[e].y +
                       acc[e].z * acc[e].z + acc[e].w * acc[e].w;
            s1 = warp_sum(s1); s2 = warp_sum(s2);
            float mu = s1 * 0.0078125f;
            float var = s2 * 0.0078125f - mu * mu;
            float rs = rsqrtf(var + EPSn);
            float4 g = gc4[lane], b = bc4[lane];
            float4 h;
            h.x = fmaxf((acc[e].x - mu) * rs * g.x + b.x, 0.f);
            h.y = fmaxf((acc[e].y - mu) * rs * g.y + b.y, 0.f);
            h.z = fmaxf((acc[e].z - mu) * rs * g.z + b.z, 0.f);
            h.w = fmaxf((acc[e].w - mu) * rs * g.w + b.w, 0.f);
            ((float4*)(xw + e * 256))[lane] = h;
        }
        __syncwarp();

        // GEMM2: [4,128] @ [128,128]
        float4 acc2[4];
#pragma unroll
        for (int e = 0; e < 4; e++) acc2[e] = make_float4(0.f, 0.f, 0.f, 0.f);
#pragma unroll 4
        for (int k = 0; k < Dm; k++) {
            float4 w = W24[k * 32 + lane];
#pragma unroll
            for (int e = 0; e < 4; e++) {
                float xv = xw[e * 256 + k];
                acc2[e].x += xv * w.x; acc2[e].y += xv * w.y;
                acc2[e].z += xv * w.z; acc2[e].w += xv * w.w;
            }
        }
        // scatter-add
#pragma unroll
        for (int e = 0; e < 4; e++) {
            if (e < ne) {
                float* dst = g_tf + widx[e] * Dm + 4 * lane;
                atomicAdd(dst + 0, acc2[e].x);
                atomicAdd(dst + 1, acc2[e].y);
                atomicAdd(dst + 2, acc2[e].z);
                atomicAdd(dst + 3, acc2[e].w);
            }
        }
        __syncwarp();
    }
}

// ---------------------------------------------------------------------------
// K3: per-row tail:
//   a = relu(GN(tf; g_n, be_n))
//   b = relu(GN(a @ W_m1; g_m1, be_m1))
//   c = GN(b @ W_m2; g_m2, be_m2)
//   out = relu(c + target_feat)
// blockDim = 256 (8 warps), warp handles 4 rows.
// smem floats: Wm1 16384 | Wm2 16384 | params 768 | xs 8*4*128 = 37632 f = 150528 B
// ---------------------------------------------------------------------------
extern "C" __global__ void __launch_bounds__(256)
k3_post(const float* __restrict__ tfeat,
        const float* __restrict__ gn,  const float* __restrict__ ben,
        const float* __restrict__ Wm1, const float* __restrict__ g1,
        const float* __restrict__ b1,  const float* __restrict__ Wm2,
        const float* __restrict__ g2,  const float* __restrict__ b2,
        float* __restrict__ out, int Nt) {
    extern __shared__ float sm[];
    float* W1s = sm;                 // 16384
    float* W2s = W1s + 16384;        // 16384
    float* ps  = W2s + 16384;        // 6*128
    float* xs  = ps + 768;           // 8*4*128

    int tid = threadIdx.x;
    {
        const float4* a = (const float4*)Wm1; float4* b_ = (float4*)W1s;
        for (int i = tid; i < 4096; i += blockDim.x) b_[i] = a[i];
        const float4* c = (const float4*)Wm2; float4* d = (float4*)W2s;
        for (int i = tid; i < 4096; i += blockDim.x) d[i] = c[i];
    }
    for (int i = tid; i < 128; i += blockDim.x) {
        ps[i]       = gn[i];  ps[128 + i] = ben[i];
        ps[256 + i] = g1[i];  ps[384 + i] = b1[i];
        ps[512 + i] = g2[i];  ps[640 + i] = b2[i];
    }
    __syncthreads();

    int lane = tid & 31, warp = tid >> 5;
    float* xw = xs + warp * 4 * Dm;
    const float4* W14 = (const float4*)W1s;
    const float4* W24 = (const float4*)W2s;
    const float4* gn4  = (const float4*)(ps);
    const float4* ben4 = (const float4*)(ps + 128);
    const float4* g14  = (const float4*)(ps + 256);
    const float4* b14  = (const float4*)(ps + 384);
    const float4* g24  = (const float4*)(ps + 512);
    const float4* b24  = (const float4*)(ps + 640);
    const float4* id4  = (const float4*)tfeat;

    int nwarp = blockDim.x >> 5;
    int gw = blockIdx.x * nwarp + warp;
    int wt = gridDim.x * nwarp;

    for (int base = gw * 4; base < Nt; base += wt * 4) {
        int ne = min(4, Nt - base);
        // GN1 over tf rows -> a in xs
#pragma unroll
        for (int e = 0; e < 4; e++) {
            int r = base + ((e < ne) ? e : 0);
            float4 v = ((const float4*)(g_tf + r * Dm))[lane];
            float s1 = v.x + v.y + v.z + v.w;
            float s2 = v.x * v.x + v.y * v.y + v.z * v.z + v.w * v.w;
            s1 = warp_sum(s1); s2 = warp_sum(s2);
            float mu = s1 * 0.0078125f;
            float var = s2 * 0.0078125f - mu * mu;
            float rs = rsqrtf(var + EPSn);
            float4 g = gn4[lane], b = ben4[lane];
            float4 a;
            a.x = fmaxf((v.x - mu) * rs * g.x + b.x, 0.f);
            a.y = fmaxf((v.y - mu) * rs * g.y + b.y, 0.f);
            a.z = fmaxf((v.z - mu) * rs * g.z + b.z, 0.f);
            a.w = fmaxf((v.w - mu) * rs * g.w + b.w, 0.f);
            ((float4*)(xw + e * Dm))[lane] = a;
        }
        __syncwarp();

        // GEMV1 + GN + relu -> xs
        float4 acc[4];
#pragma unroll
        for (int e = 0; e < 4; e++) acc[e] = make_float4(0.f, 0.f, 0.f, 0.f);
#pragma unroll 4
        for (int k = 0; k < Dm; k++) {
            float4 w = W14[k * 32 + lane];
#pragma unroll
            for (int e = 0; e < 4; e++) {
                float xv = xw[e * Dm + k];
                acc[e].x += xv * w.x; acc[e].y += xv * w.y;
                acc[e].z += xv * w.z; acc[e].w += xv * w.w;
            }
        }
#pragma unroll
        for (int e = 0; e < 4; e++) {
            float s1 = acc[e].x + acc[e].y + acc[e].z + acc[e].w;
            float s2 = acc[e].x * acc[e].x + acc[e].y * acc[e].y +
                       acc[e].z * acc[e].z + acc[e].w * acc[e].w;
            s1 = warp_sum(s1); s2 = warp_sum(s2);
            float mu = s1 * 0.0078125f;
            float var = s2 * 0.0078125f - mu * mu;
            float rs = rsqrtf(var + EPSn);
            float4 g = g14[lane], b = b14[lane];
            float4 h;
            h.x = fmaxf((acc[e].x - mu) * rs * g.x + b.x, 0.f);
            h.y = fmaxf((acc[e].y - mu) * rs * g.y + b.y, 0.f);
            h.z = fmaxf((acc[e].z - mu) * rs * g.z + b.z, 0.f);
            h.w = fmaxf((acc[e].w - mu) * rs * g.w + b.w, 0.f);
            ((float4*)(xw + e * Dm))[lane] = h;
        }
        __syncwarp();

        // GEMV2 + GN + add identity + relu -> out
        float4 acc2[4];
#pragma unroll
        for (int e = 0; e < 4; e++) acc2[e] = make_float4(0.f, 0.f, 0.f, 0.f);
#pragma unroll 4
        for (int k = 0; k < Dm; k++) {
            float4 w = W24[k * 32 + lane];
#pragma unroll
            for (int e = 0; e < 4; e++) {
                float xv = xw[e * Dm + k];
                acc2[e].x += xv * w.x; acc2[e].y += xv * w.y;
                acc2[e].z += xv * w.z; acc2[e].w += xv * w.w;
            }
        }
#pragma unroll
        for (int e = 0; e < 4; e++) {
            if (e >= ne) break;
            int r = base + e;
            float s1 = acc2[e].x + acc2[e].y + acc2[e].z + acc2[e].w;
            float s2 = acc2[e].x * acc2[e].x + acc2[e].y * acc2[e].y +
                       acc2[e].z * acc2[e].z + acc2[e].w * acc2[e].w;
            s1 = warp_sum(s1); s2 = warp_sum(s2);
            float mu = s1 * 0.0078125f;
            float var = s2 * 0.0078125f - mu * mu;
            float rs = rsqrtf(var + EPSn);
            float4 g = g24[lane], b = b24[lane];
            float4 idv = id4[r * 32 + lane];
            float4 o;
            o.x = fmaxf((acc2[e].x - mu) * rs * g.x + b.x + idv.x, 0.f);
            o.y = fmaxf((acc2[e].y - mu) * rs * g.y + b.y + idv.y, 0.f);
            o.z = fmaxf((acc2[e].z - mu) * rs * g.z + b.z + idv.z, 0.f);
            o.w = fmaxf((acc2[e].w - mu) * rs * g.w + b.w + idv.w, 0.f);
            ((float4*)(out + r * Dm))[lane] = o;
        }
        __syncwarp();
    }
}

// ---------------------------------------------------------------------------
// launch
// ---------------------------------------------------------------------------
extern "C" void kernel_launch(void* const* d_in, const int* in_sizes, int n_in,
                              void* d_out, int out_size) {
    const float* context_feat = (const float*)d_in[0];
    const float* target_feat  = (const float*)d_in[1];
    const float* context_pose = (const float*)d_in[2];
    const float* target_pose  = (const float*)d_in[3];
    const int*   hi    = (const int*)d_in[4];
    const int*   wi    = (const int*)d_in[5];
    const float* W_in  = (const float*)d_in[6];
    const float* W_rp  = (const float*)d_in[7];
    const float* b_rp  = (const float*)d_in[8];
    const float* W_c1  = (const float*)d_in[9];
    const float* g_ctx = (const float*)d_in[10];
    const float* be_ctx= (const float*)d_in[11];
    const float* W_c2  = (const float*)d_in[12];
    const float* g_n   = (const float*)d_in[13];
    const float* be_n  = (const float*)d_in[14];
    const float* W_m1  = (const float*)d_in[15];
    const float* g_m1  = (const float*)d_in[16];
    const float* be_m1 = (const float*)d_in[17];
    const float* W_m2  = (const float*)d_in[18];
    const float* g_m2  = (const float*)d_in[19];
    const float* be_m2 = (const float*)d_in[20];

    int Nt = in_sizes[1] / 128;
    int E  = in_sizes[4];
    float* out = (float*)d_out;

    const int SM1 = (16384 + 8 * 4 * 128) * 4;                    // 81920
    const int SM2 = (512 + 128 * 3 + 32768 + 16384 + 6 * 4 * 256) * 4;  // 224768
    const int SM3 = (16384 + 16384 + 768 + 8 * 4 * 128) * 4;      // 150528

    cudaFuncSetAttribute(k1_proj, cudaFuncAttributeMaxDynamicSharedMemorySize, SM1);
    cudaFuncSetAttribute(k2_edge, cudaFuncAttributeMaxDynamicSharedMemorySize, SM2);
    cudaFuncSetAttribute(k3_post, cudaFuncAttributeMaxDynamicSharedMemorySize, SM3);

    k1_proj<<<296, 256, SM1>>>(target_feat, W_in, Nt);
    k2_edge<<<148, 192, SM2>>>(context_feat, context_pose, target_pose, hi, wi,
                               W_rp, b_rp, W_c1, g_ctx, be_ctx, W_c2, E);
    k3_post<<<148, 256, SM3>>>(target_feat, g_n, be_n, W_m1, g_m1, be_m1,
                               W_m2, g_m2, be_m2, out, Nt);
}

// round 4
// speedup vs baseline: 1.9690x; 1.9690x over previous
#include <cuda_runtime.h>
#include <cuda_bf16.h>

#define Dm 128
#define EPSn 1e-5f

// ---------------- device scratch (no allocs allowed) ----------------
__device__ float g_tf[100000 * 128];
__device__ __align__(256) __nv_bfloat16 g_W1t_h[128 * 256];  // W_ctx1^T [n][k] hi
__device__ __align__(256) __nv_bfloat16 g_W1t_l[128 * 256];  // lo
__device__ __align__(256) __nv_bfloat16 g_W2t_h[128 * 128];  // W_ctx2^T hi
__device__ __align__(256) __nv_bfloat16 g_W2t_l[128 * 128];  // lo

__device__ __forceinline__ unsigned su32(const void* p) {
    unsigned a;
    asm("{ .reg .u64 t; cvta.to.shared.u64 t, %1; cvt.u32.u64 %0, t; }"
        : "=r"(a) : "l"(p));
    return a;
}

__device__ __forceinline__ void mma_bf16(float* c, unsigned a0, unsigned a1,
                                         unsigned a2, unsigned a3,
                                         unsigned b0, unsigned b1) {
    asm volatile(
        "mma.sync.aligned.m16n8k16.row.col.f32.bf16.bf16.f32 "
        "{%0,%1,%2,%3},{%4,%5,%6,%7},{%8,%9},{%0,%1,%2,%3};"
        : "+f"(c[0]), "+f"(c[1]), "+f"(c[2]), "+f"(c[3])
        : "r"(a0), "r"(a1), "r"(a2), "r"(a3), "r"(b0), "r"(b1));
}

__device__ __forceinline__ void split2(float a, float b, unsigned& h, unsigned& l) {
    __nv_bfloat16 ah = __float2bfloat16(a);
    __nv_bfloat16 bh = __float2bfloat16(b);
    __nv_bfloat16 al = __float2bfloat16(a - __bfloat162float(ah));
    __nv_bfloat16 bl = __float2bfloat16(b - __bfloat162float(bh));
    __nv_bfloat162 hp; hp.x = ah; hp.y = bh;
    __nv_bfloat162 lp; lp.x = al; lp.y = bl;
    h = *(unsigned*)&hp;
    l = *(unsigned*)&lp;
}

__device__ __forceinline__ float warp_sum(float v) {
    v += __shfl_xor_sync(0xffffffffu, v, 16);
    v += __shfl_xor_sync(0xffffffffu, v, 8);
    v += __shfl_xor_sync(0xffffffffu, v, 4);
    v += __shfl_xor_sync(0xffffffffu, v, 2);
    v += __shfl_xor_sync(0xffffffffu, v, 1);
    return v;
}

// ---------------------------------------------------------------------------
// K0: split/transpose weights to bf16 hi/lo in [n][k] layout
// ---------------------------------------------------------------------------
extern "C" __global__ void k0_prep(const float* __restrict__ W1,
                                   const float* __restrict__ W2) {
    int i = blockIdx.x * blockDim.x + threadIdx.x;
    if (i < 128 * 256) {
        int n = i >> 8, k = i & 255;
        float v = W1[k * 128 + n];
        __nv_bfloat16 h = __float2bfloat16(v);
        g_W1t_h[i] = h;
        g_W1t_l[i] = __float2bfloat16(v - __bfloat162float(h));
    }
    if (i < 128 * 128) {
        int n = i >> 7, k = i & 127;
        float v = W2[k * 128 + n];
        __nv_bfloat16 h = __float2bfloat16(v);
        g_W2t_h[i] = h;
        g_W2t_l[i] = __float2bfloat16(v - __bfloat162float(h));
    }
}

// ---------------------------------------------------------------------------
// K1: g_tf = target_feat @ W_in  (SIMT)
// ---------------------------------------------------------------------------
extern "C" __global__ void __launch_bounds__(256)
k1_proj(const float* __restrict__ tfeat, const float* __restrict__ Win, int Nt) {
    extern __shared__ float sm[];
    float* Ws = sm;
    float* xs = sm + Dm * Dm;

    int tid = threadIdx.x;
    {
        const float4* a = (const float4*)Win;
        float4* b = (float4*)Ws;
        for (int i = tid; i < Dm * Dm / 4; i += blockDim.x) b[i] = a[i];
    }
    __syncthreads();

    int lane = tid & 31, warp = tid >> 5;
    float* xw = xs + warp * 4 * Dm;
    const float4* W4 = (const float4*)Ws;
    const float4* x4 = (const float4*)tfeat;

    int nwarp = blockDim.x >> 5;
    int gw = blockIdx.x * nwarp + warp;
    int wt = gridDim.x * nwarp;

    for (int base = gw * 4; base < Nt; base += wt * 4) {
        int ne = min(4, Nt - base);
#pragma unroll
        for (int e = 0; e < 4; e++) {
            int r = base + ((e < ne) ? e : 0);
            ((float4*)(xw + e * Dm))[lane] = x4[r * 32 + lane];
        }
        __syncwarp();
        float4 acc[4];
#pragma unroll
        for (int e = 0; e < 4; e++) acc[e] = make_float4(0.f, 0.f, 0.f, 0.f);
#pragma unroll 4
        for (int k = 0; k < Dm; k++) {
            float4 w = W4[k * 32 + lane];
#pragma unroll
            for (int e = 0; e < 4; e++) {
                float xv = xw[e * Dm + k];
                acc[e].x += xv * w.x; acc[e].y += xv * w.y;
                acc[e].z += xv * w.z; acc[e].w += xv * w.w;
            }
        }
#pragma unroll
        for (int e = 0; e < 4; e++)
            if (e < ne) ((float4*)(g_tf + (size_t)(base + e) * Dm))[lane] = acc[e];
        __syncwarp();
    }
}

// ---------------------------------------------------------------------------
// K2 (mma.sync bf16 hi/lo): 1 CTA/SM, 256 threads = 8 warps, tile = 128 edges.
// ---------------------------------------------------------------------------
extern "C" __global__ void __launch_bounds__(256, 1)
k2mma(const float* __restrict__ cfeat, const float* __restrict__ cpose,
      const float* __restrict__ tpose, const int* __restrict__ hiA,
      const int* __restrict__ wiA, const float* __restrict__ Wrp,
      const float* __restrict__ brp, const float* __restrict__ gcv,
      const float* __restrict__ bcv, int E) {
    extern __shared__ char smem[];
    unsigned* XH  = (unsigned*)smem;      // [128][64]
    unsigned* XL  = XH + 8192;
    unsigned* W1H = XL + 8192;
    unsigned* W1L = W1H + 8192;
    unsigned* W2H = W1L + 8192;
    unsigned* W2L = W2H + 8192;
    float* wrp_s = (float*)(W2L + 8192);  // 512
    float* brp_s = wrp_s + 512;           // 128
    float* gc_s  = brp_s + 128;           // 128
    float* bc_s  = gc_s + 128;            // 128
    int* hid = (int*)(bc_s + 128);        // 128
    int* wid = hid + 128;                 // 128

    const int tid = threadIdx.x;

    // resident W2 (swizzled) + params
    for (int i = tid; i < 8192; i += 256) {
        int n = i >> 6, w = i & 63;
        int d = n * 64 + (w ^ ((n & 7) << 2));
        W2H[d] = ((const unsigned*)g_W2t_h)[i];
        W2L[d] = ((const unsigned*)g_W2t_l)[i];
    }
    for (int i = tid; i < 512; i += 256) wrp_s[i] = Wrp[i];
    if (tid < 128) { brp_s[tid] = brp[tid]; gc_s[tid] = gcv[tid]; bc_s[tid] = bcv[tid]; }

    const unsigned sW1H = su32(W1H), sW1L = su32(W1L);
    auto prefetchW1 = [&](int hf) {
        const char* gH = (const char*)g_W1t_h;
        const char* gL = (const char*)g_W1t_l;
#pragma unroll
        for (int j = 0; j < 8; j++) {
            int c = tid * 8 + j;               // 0..2047 chunks of 16B
            int n = c >> 4, w0 = (c & 15) << 2;
            unsigned dst = (unsigned)((n * 64 + (w0 ^ ((n & 7) << 2))) * 4);
            size_t src = (size_t)n * 512 + (size_t)hf * 256 + (size_t)w0 * 4;
            asm volatile("cp.async.cg.shared.global [%0], [%1], 16;"
                         :: "r"(sW1H + dst), "l"(gH + src));
            asm volatile("cp.async.cg.shared.global [%0], [%1], 16;"
                         :: "r"(sW1L + dst), "l"(gL + src));
        }
        asm volatile("cp.async.commit_group;" ::: "memory");
    };

    const int warp = tid >> 5, lane = tid & 31;
    const int g = lane >> 2, t = lane & 3;
    const int r0 = warp * 16 + g;                 // this lane's A row
    const unsigned sg = (unsigned)(g << 2);       // swizzle term (r0&7 == g)
    const int ntiles = (E + 127) >> 7;

    float acc[16][4];

    prefetchW1(0);
    __syncthreads();

    auto gemmK = [&](unsigned* WH, unsigned* WL) {
        unsigned* xh = XH + r0 * 64;
        unsigned* xl = XL + r0 * 64;
#pragma unroll
        for (int ks = 0; ks < 8; ks++) {
            unsigned o  = (unsigned)(8 * ks + t) ^ sg;
            unsigned o4 = (unsigned)(8 * ks + t + 4) ^ sg;
            unsigned ah0 = xh[o],  ah1 = xh[512 + o];
            unsigned ah2 = xh[o4], ah3 = xh[512 + o4];
            unsigned al0 = xl[o],  al1 = xl[512 + o];
            unsigned al2 = xl[o4], al3 = xl[512 + o4];
#pragma unroll
            for (int nb = 0; nb < 16; nb++) {
                unsigned* wh = WH + (8 * nb + g) * 64;
                unsigned* wl = WL + (8 * nb + g) * 64;
                unsigned bh0 = wh[o], bh1 = wh[o4];
                unsigned bl0 = wl[o], bl1 = wl[o4];
                mma_bf16(acc[nb], ah0, ah1, ah2, ah3, bh0, bh1);
                mma_bf16(acc[nb], al0, al1, al2, al3, bh0, bh1);
                mma_bf16(acc[nb], ah0, ah1, ah2, ah3, bl0, bl1);
            }
        }
    };

    for (int tile = blockIdx.x; tile < ntiles; tile += gridDim.x) {
        const int base = tile << 7;
        if (tid < 128) {
            int e = base + tid;
            int ec = e < E ? e : (E - 1);
            hid[tid] = hiA[ec];
            wid[tid] = wiA[ec];
        }
        __syncthreads();

        // ---- build x (k 0..127) = gathered context feats ----
        {
            int row = tid >> 1, hf = tid & 1;
            const float4* src = (const float4*)(cfeat + (size_t)hid[row] * 128) + hf * 16;
            unsigned s = (unsigned)((row & 7) << 2);
            unsigned* xh = XH + row * 64;
            unsigned* xl = XL + row * 64;
#pragma unroll
            for (int q = 0; q < 16; q++) {
                float4 f = src[q];
                unsigned h0, l0, h1, l1;
                split2(f.x, f.y, h0, l0);
                split2(f.z, f.w, h1, l1);
                int d = (hf * 32 + 2 * q) ^ s;
                xh[d] = h0; xh[d + 1] = h1;
                xl[d] = l0; xl[d + 1] = l1;
            }
        }
        asm volatile("cp.async.wait_group 0;" ::: "memory");
        __syncthreads();

#pragma unroll
        for (int nb = 0; nb < 16; nb++) {
            acc[nb][0] = 0.f; acc[nb][1] = 0.f; acc[nb][2] = 0.f; acc[nb][3] = 0.f;
        }
        gemmK(W1H, W1L);          // k-half 0 of GEMM1
        __syncthreads();
        prefetchW1(1);

        // ---- build x (k 128..255) = relpose MLP ----
        {
            int row = tid >> 1, hf = tid & 1;
            float4 cp = *(const float4*)(cpose + 4 * (size_t)hid[row]);
            float4 tp = *(const float4*)(tpose + 4 * (size_t)wid[row]);
            float d0 = cp.x - tp.x, d1 = cp.y - tp.y;
            float d2 = cp.z - tp.z, d3 = cp.w - tp.w;
            unsigned s = (unsigned)((row & 7) << 2);
            unsigned* xh = XH + row * 64;
            unsigned* xl = XL + row * 64;
#pragma unroll 8
            for (int q = 0; q < 32; q++) {
                int c0 = hf * 64 + 2 * q;
                float a = fmaxf(brp_s[c0] + d0 * wrp_s[c0] + d1 * wrp_s[128 + c0] +
                                d2 * wrp_s[256 + c0] + d3 * wrp_s[384 + c0], 0.f);
                float b = fmaxf(brp_s[c0 + 1] + d0 * wrp_s[c0 + 1] + d1 * wrp_s[128 + c0 + 1] +
                                d2 * wrp_s[256 + c0 + 1] + d3 * wrp_s[384 + c0 + 1], 0.f);
                unsigned hh, ll;
                split2(a, b, hh, ll);
                int d = (hf * 32 + q) ^ s;
                xh[d] = hh; xl[d] = ll;
            }
        }
        asm volatile("cp.async.wait_group 0;" ::: "memory");
        __syncthreads();

        gemmK(W1H, W1L);          // k-half 1 of GEMM1
        __syncthreads();
        prefetchW1(0);            // next tile's half0; hidden under epilogue+GEMM2

        // ---- epilogue 1: GroupNorm + relu -> h (bf16 hi/lo back into XH/XL) ----
        {
            float s1a = 0.f, s2a = 0.f, s1b = 0.f, s2b = 0.f;
#pragma unroll
            for (int nb = 0; nb < 16; nb++) {
                s1a += acc[nb][0] + acc[nb][1];
                s2a += acc[nb][0] * acc[nb][0] + acc[nb][1] * acc[nb][1];
                s1b += acc[nb][2] + acc[nb][3];
                s2b += acc[nb][2] * acc[nb][2] + acc[nb][3] * acc[nb][3];
            }
#pragma unroll
            for (int off = 1; off <= 2; off <<= 1) {
                s1a += __shfl_xor_sync(0xffffffffu, s1a, off);
                s2a += __shfl_xor_sync(0xffffffffu, s2a, off);
                s1b += __shfl_xor_sync(0xffffffffu, s1b, off);
                s2b += __shfl_xor_sync(0xffffffffu, s2b, off);
            }
            float mua = s1a * 0.0078125f;
            float rsa = rsqrtf(s2a * 0.0078125f - mua * mua + EPSn);
            float mub = s1b * 0.0078125f;
            float rsb = rsqrtf(s2b * 0.0078125f - mub * mub + EPSn);

            unsigned* xh = XH + r0 * 64;
            unsigned* xl = XL + r0 * 64;
#pragma unroll
            for (int nb = 0; nb < 16; nb++) {
                int c0 = 8 * nb + 2 * t;
                float ga = gc_s[c0], gb = gc_s[c0 + 1];
                float ba = bc_s[c0], bb = bc_s[c0 + 1];
                float h0 = fmaxf((acc[nb][0] - mua) * rsa * ga + ba, 0.f);
                float h1 = fmaxf((acc[nb][1] - mua) * rsa * gb + bb, 0.f);
                float h2 = fmaxf((acc[nb][2] - mub) * rsb * ga + ba, 0.f);
                float h3 = fmaxf((acc[nb][3] - mub) * rsb * gb + bb, 0.f);
                unsigned p0, q0, p1, q1;
                split2(h0, h1, p0, q0);
                split2(h2, h3, p1, q1);
                unsigned d = (unsigned)(4 * nb + t) ^ sg;
                xh[d] = p0; xh[512 + d] = p1;
                xl[d] = q0; xl[512 + d] = q1;
            }
        }
        __syncthreads();

        // ---- GEMM2: ctx = h @ W_ctx2 ----
#pragma unroll
        for (int nb = 0; nb < 16; nb++) {
            acc[nb][0] = 0.f; acc[nb][1] = 0.f; acc[nb][2] = 0.f; acc[nb][3] = 0.f;
        }
        gemmK(W2H, W2L);
        __syncthreads();          // all warps done reading h before staging overwrite

        // ---- epilogue 2: stage acc (f32) into XH/XL region ----
        {
            float2* st = (float2*)smem;          // [128][64] float2
            float2* sa = st + r0 * 64;
#pragma unroll
            for (int nb = 0; nb < 16; nb++) {
                unsigned d = (unsigned)(4 * nb + t) ^ sg;
                sa[d]       = make_float2(acc[nb][0], acc[nb][1]);
                sa[512 + d] = make_float2(acc[nb][2], acc[nb][3]);
            }
        }
        __syncthreads();

        // ---- vector scatter-add into g_tf ----
        {
            int row = tid >> 1, hq = tid & 1;
            if (base + row < E) {
                float* dst = g_tf + (size_t)wid[row] * 128;
                float2* rp = (float2*)smem + row * 64;
                unsigned s = (unsigned)((row & 7) << 2);
#pragma unroll
                for (int j = 0; j < 16; j++) {
                    int c = hq * 16 + j;                 // float4 chunk 0..31
                    unsigned d2 = (unsigned)(2 * c) ^ s; // even -> 16B aligned
                    float4 v = *(const float4*)(rp + d2);
                    asm volatile("red.global.add.v4.f32 [%0], {%1,%2,%3,%4};"
                                 :: "l"(dst + 4 * c),
                                    "f"(v.x), "f"(v.y), "f"(v.z), "f"(v.w)
                                 : "memory");
                }
            }
        }
        __syncthreads();
    }
}

// ---------------------------------------------------------------------------
// K3: per-row tail (SIMT)
// ---------------------------------------------------------------------------
extern "C" __global__ void __launch_bounds__(256)
k3_post(const float* __restrict__ tfeat,
        const float* __restrict__ gn,  const float* __restrict__ ben,
        const float* __restrict__ Wm1, const float* __restrict__ g1,
        const float* __restrict__ b1,  const float* __restrict__ Wm2,
        const float* __restrict__ g2,  const float* __restrict__ b2,
        float* __restrict__ out, int Nt) {
    extern __shared__ float sm[];
    float* W1s = sm;
    float* W2s = W1s + 16384;
    float* ps  = W2s + 16384;
    float* xs  = ps + 768;

    int tid = threadIdx.x;
    {
        const float4* a = (const float4*)Wm1; float4* b_ = (float4*)W1s;
        for (int i = tid; i < 4096; i += blockDim.x) b_[i] = a[i];
        const float4* c = (const float4*)Wm2; float4* d = (float4*)W2s;
        for (int i = tid; i < 4096; i += blockDim.x) d[i] = c[i];
    }
    for (int i = tid; i < 128; i += blockDim.x) {
        ps[i]       = gn[i];  ps[128 + i] = ben[i];
        ps[256 + i] = g1[i];  ps[384 + i] = b1[i];
        ps[512 + i] = g2[i];  ps[640 + i] = b2[i];
    }
    __syncthreads();

    int lane = tid & 31, warp = tid >> 5;
    float* xw = xs + warp * 4 * Dm;
    const float4* W14 = (const float4*)W1s;
    const float4* W24 = (const float4*)W2s;
    const float4* gn4  = (const float4*)(ps);
    const float4* ben4 = (const float4*)(ps + 128);
    const float4* g14  = (const float4*)(ps + 256);
    const float4* b14  = (const float4*)(ps + 384);
    const float4* g24  = (const float4*)(ps + 512);
    const float4* b24  = (const float4*)(ps + 640);
    const float4* id4  = (const float4*)tfeat;

    int nwarp = blockDim.x >> 5;
    int gw = blockIdx.x * nwarp + warp;
    int wt = gridDim.x * nwarp;

    for (int base = gw * 4; base < Nt; base += wt * 4) {
        int ne = min(4, Nt - base);
#pragma unroll
        for (int e = 0; e < 4; e++) {
            int r = base + ((e < ne) ? e : 0);
            float4 v = ((const float4*)(g_tf + (size_t)r * Dm))[lane];
            float s1 = v.x + v.y + v.z + v.w;
            float s2 = v.x * v.x + v.y * v.y + v.z * v.z + v.w * v.w;
            s1 = warp_sum(s1); s2 = warp_sum(s2);
            float mu = s1 * 0.0078125f;
            float var = s2 * 0.0078125f - mu * mu;
            float rs = rsqrtf(var + EPSn);
            float4 g = gn4[lane], b = ben4[lane];
            float4 a;
            a.x = fmaxf((v.x - mu) * rs * g.x + b.x, 0.f);
            a.y = fmaxf((v.y - mu) * rs * g.y + b.y, 0.f);
            a.z = fmaxf((v.z - mu) * rs * g.z + b.z, 0.f);
            a.w = fmaxf((v.w - mu) * rs * g.w + b.w, 0.f);
            ((float4*)(xw + e * Dm))[lane] = a;
        }
        __syncwarp();

        float4 acc[4];
#pragma unroll
        for (int e = 0; e < 4; e++) acc[e] = make_float4(0.f, 0.f, 0.f, 0.f);
#pragma unroll 4
        for (int k = 0; k < Dm; k++) {
            float4 w = W14[k * 32 + lane];
#pragma unroll
            for (int e = 0; e < 4; e++) {
                float xv = xw[e * Dm + k];
                acc[e].x += xv * w.x; acc[e].y += xv * w.y;
                acc[e].z += xv * w.z; acc[e].w += xv * w.w;
            }
        }
#pragma unroll
        for (int e = 0; e < 4; e++) {
            float s1 = acc[e].x + acc[e].y + acc[e].z + acc[e].w;
            float s2 = acc[e].x * acc[e].x + acc[e].y * acc[e].y +
                       acc[e].z * acc[e].z + acc[e].w * acc[e].w;
            s1 = warp_sum(s1); s2 = warp_sum(s2);
            float mu = s1 * 0.0078125f;
            float var = s2 * 0.0078125f - mu * mu;
            float rs = rsqrtf(var + EPSn);
            float4 g = g14[lane], b = b14[lane];
            float4 h;
            h.x = fmaxf((acc[e].x - mu) * rs * g.x + b.x, 0.f);
            h.y = fmaxf((acc[e].y - mu) * rs * g.y + b.y, 0.f);
            h.z = fmaxf((acc[e].z - mu) * rs * g.z + b.z, 0.f);
            h.w = fmaxf((acc[e].w - mu) * rs * g.w + b.w, 0.f);
            ((float4*)(xw + e * Dm))[lane] = h;
        }
        __syncwarp();

        float4 acc2[4];
#pragma unroll
        for (int e = 0; e < 4; e++) acc2[e] = make_float4(0.f, 0.f, 0.f, 0.f);
#pragma unroll 4
        for (int k = 0; k < Dm; k++) {
            float4 w = W24[k * 32 + lane];
#pragma unroll
            for (int e = 0; e < 4; e++) {
                float xv = xw[e * Dm + k];
                acc2[e].x += xv * w.x; acc2[e].y += xv * w.y;
                acc2[e].z += xv * w.z; acc2[e].w += xv * w.w;
            }
        }
#pragma unroll
        for (int e = 0; e < 4; e++) {
            if (e >= ne) break;
            int r = base + e;
            float s1 = acc2[e].x + acc2[e].y + acc2[e].z + acc2[e].w;
            float s2 = acc2[e].x * acc2[e].x + acc2[e].y * acc2[e].y +
                       acc2[e].z * acc2[e].z + acc2[e].w * acc2[e].w;
            s1 = warp_sum(s1); s2 = warp_sum(s2);
            float mu = s1 * 0.0078125f;
            float var = s2 * 0.0078125f - mu * mu;
            float rs = rsqrtf(var + EPSn);
            float4 g = g24[lane], b = b24[lane];
            float4 idv = id4[r * 32 + lane];
            float4 o;
            o.x = fmaxf((acc2[e].x - mu) * rs * g.x + b.x + idv.x, 0.f);
            o.y = fmaxf((acc2[e].y - mu) * rs * g.y + b.y + idv.y, 0.f);
            o.z = fmaxf((acc2[e].z - mu) * rs * g.z + b.z + idv.z, 0.f);
            o.w = fmaxf((acc2[e].w - mu) * rs * g.w + b.w + idv.w, 0.f);
            ((float4*)(out + (size_t)r * Dm))[lane] = o;
        }
        __syncwarp();
    }
}

// ---------------------------------------------------------------------------
// launch
// ---------------------------------------------------------------------------
extern "C" void kernel_launch(void* const* d_in, const int* in_sizes, int n_in,
                              void* d_out, int out_size) {
    const float* context_feat = (const float*)d_in[0];
    const float* target_feat  = (const float*)d_in[1];
    const float* context_pose = (const float*)d_in[2];
    const float* target_pose  = (const float*)d_in[3];
    const int*   hi    = (const int*)d_in[4];
    const int*   wi    = (const int*)d_in[5];
    const float* W_in  = (const float*)d_in[6];
    const float* W_rp  = (const float*)d_in[7];
    const float* b_rp  = (const float*)d_in[8];
    const float* W_c1  = (const float*)d_in[9];
    const float* g_ctx = (const float*)d_in[10];
    const float* be_ctx= (const float*)d_in[11];
    const float* W_c2  = (const float*)d_in[12];
    const float* g_n   = (const float*)d_in[13];
    const float* be_n  = (const float*)d_in[14];
    const float* W_m1  = (const float*)d_in[15];
    const float* g_m1  = (const float*)d_in[16];
    const float* be_m1 = (const float*)d_in[17];
    const float* W_m2  = (const float*)d_in[18];
    const float* g_m2  = (const float*)d_in[19];
    const float* be_m2 = (const float*)d_in[20];

    int Nt = in_sizes[1] / 128;
    int E  = in_sizes[4];
    float* out = (float*)d_out;

    const int SM1 = (16384 + 8 * 4 * 128) * 4;
    const int SM2 = 6 * 32768 + 896 * 4 + 1024;   // 201216 B
    const int SM3 = (16384 + 16384 + 768 + 8 * 4 * 128) * 4;

    cudaFuncSetAttribute(k1_proj, cudaFuncAttributeMaxDynamicSharedMemorySize, SM1);
    cudaFuncSetAttribute(k2mma,  cudaFuncAttributeMaxDynamicSharedMemorySize, SM2);
    cudaFuncSetAttribute(k3_post, cudaFuncAttributeMaxDynamicSharedMemorySize, SM3);

    k0_prep<<<128, 256>>>(W_c1, W_c2);
    k1_proj<<<296, 256, SM1>>>(target_feat, W_in, Nt);
    k2mma<<<148, 256, SM2>>>(context_feat, context_pose, target_pose, hi, wi,
                             W_rp, b_rp, g_ctx, be_ctx, E);
    k3_post<<<148, 256, SM3>>>(target_feat, g_n, be_n, W_m1, g_m1, be_m1,
                               W_m2, g_m2, be_m2, out, Nt);
}